// round 2
// baseline (speedup 1.0000x reference)
#include <cuda_runtime.h>
#include <math.h>

// SpikingLayer: T=500, B=16, n_syn=1, N=4096 (65536 neurons, each an independent
// 500-step threshold/refractory scan over a 149-tap causal EPSP convolution).
//
// Correctness strategy: the system is threshold-chaotic, so we must reproduce the
// reference's fp32 ROUNDING, not just the true math. The reference conv (XLA:CPU ->
// Eigen im2col GEMM) accumulates each output sequentially over the 149 taps in
// patch order (oldest history first) with f32 FMA. Since x is binary, that equals:
// sum of k[j] over set history bits, j descending 148..0, plain f32 adds.
// We keep a 160-bit spike-history shift register per thread and do exactly that,
// using the epsp_kernel input values (the exact f32 constants the reference used).

#define TBN 65536   // B*N neurons
#define T_STEPS 500
#define UF 20       // 500 = 25 * 20
#define BLK 128

__global__ __launch_bounds__(BLK)
void SpikingLayer_90202903151092_kernel(const float* __restrict__ x,
                                        const float* __restrict__ ker,
                                        float* __restrict__ out) {
    __shared__ float ks[152];

    // stage the 149 kernel taps (exact f32 values used by the reference)
    for (int i = threadIdx.x; i < 149; i += BLK) ks[i] = ker[i];
    __syncthreads();

    const int idx = blockIdx.x * BLK + threadIdx.x;   // neuron id
    const float* xp = x + idx;
    float*       op = out + idx;

    // alpha = f32(exp(-dt/tau_mem)); arg perturbation from f32(-0.1) is far below
    // half-ulp of the result, so this matches XLA's f32 exp output.
    const float alpha = 0.9048374180359595f;

    // 160-bit history: bit j (word j>>5, bit j&31) = x[t - j] after the shift.
    unsigned h0 = 0u, h1 = 0u, h2 = 0u, h3 = 0u, h4 = 0u;
    float r = 0.0f;

    #pragma unroll 1
    for (int t0 = 0; t0 < T_STEPS; t0 += UF) {
        // front-batched streaming loads (20 independent LDGs in flight)
        float xv[UF];
        #pragma unroll
        for (int i = 0; i < UF; i++)
            xv[i] = __ldcs(xp + (size_t)(t0 + i) * TBN);

        #pragma unroll
        for (int i = 0; i < UF; i++) {
            unsigned nb = (xv[i] != 0.0f) ? 1u : 0u;
            h4 = ((h4 << 1) | (h3 >> 31)) & 0x001FFFFFu;  // keep j <= 148
            h3 = (h3 << 1) | (h2 >> 31);
            h2 = (h2 << 1) | (h1 >> 31);
            h1 = (h1 << 1) | (h0 >> 31);
            h0 = (h0 << 1) | nb;

            // vmem[t] = sum over set bits of ks[j], j DESCENDING (oldest tap
            // first), strict sequential f32 adds == reference conv rounding.
            float acc = 0.0f;
            unsigned m;
            m = h4; while (m) { unsigned b = 31u - __clz(m); acc += ks[128 + b]; m &= ~(1u << b); }
            m = h3; while (m) { unsigned b = 31u - __clz(m); acc += ks[ 96 + b]; m &= ~(1u << b); }
            m = h2; while (m) { unsigned b = 31u - __clz(m); acc += ks[ 64 + b]; m &= ~(1u << b); }
            m = h1; while (m) { unsigned b = 31u - __clz(m); acc += ks[ 32 + b]; m &= ~(1u << b); }
            m = h0; while (m) { unsigned b = 31u - __clz(m); acc += ks[      b]; m &= ~(1u << b); }

            // reference scan, elementwise f32: s = (vmem + r >= 1); r = (r-s)*alpha
            float u = acc + r;
            float s = (u >= 1.0f) ? 1.0f : 0.0f;
            r = (r - s) * alpha;

            __stcs(op + (size_t)(t0 + i) * TBN, s);
        }
    }
}

extern "C" void kernel_launch(void* const* d_in, const int* in_sizes, int n_in,
                              void* d_out, int out_size) {
    const float* x   = (const float*)d_in[0];  // binary_input (500,16,1,4096) f32
    const float* ker = (const float*)d_in[1];  // epsp_kernel (1,149) f32
    float* out = (float*)d_out;                // spikes (500,16,4096) f32
    SpikingLayer_90202903151092_kernel<<<TBN / BLK, BLK>>>(x, ker, out);
}

// round 3
// speedup vs baseline: 10.3960x; 10.3960x over previous
#include <cuda_runtime.h>
#include <math.h>

// SpikingLayer T=500, B*N=65536. Hybrid scheme:
//  - cheap 2nd-order IIR reproduces the 149-tap EPSP conv to ~1e-5 abs error
//    (exact transfer function of the truncated double-exponential kernel)
//  - the spike decision u = vmem + r >= 1 is re-evaluated with the reference's
//    EXACT f32 arithmetic (sum of kernel taps over set history bits, oldest lag
//    first, sequential f32 adds == XLA conv rounding) only when |u-1| < MARGIN.
//  Decisions are therefore bit-identical to the full exact kernel (R2, passed).

#define TBN 65536
#define T_STEPS 500
#define UF 20       // 500 = 25 * 20
#define BLK 64
#define MARGIN 1e-3f

__global__ __launch_bounds__(BLK)
void SpikingLayer_90202903151092_kernel(const float* __restrict__ x,
                                        const float* __restrict__ ker,
                                        float* __restrict__ out) {
    __shared__ float ks[152];
    for (int i = threadIdx.x; i < 149; i += BLK) ks[i] = ker[i];
    __syncthreads();

    const int idx = blockIdx.x * BLK + threadIdx.x;   // neuron id
    const float* xp = x + idx;
    float*       op = out + idx;

    const float c1    = 1.7235681711139413f;    // a + b   (a=e^-0.2, b=e^-0.1)
    const float c2    = -0.7408182206817179f;   // -ab = -e^-0.3
    const float A     = 4.5399929762484854e-05f;// a^50 = b^100 = e^-10
    const float alpha = 0.9048374180359595f;    // e^-0.1 (refractory decay)

    // 160-bit spike history: bit j = x[t - j] after the shift (j <= 148 kept)
    unsigned h0 = 0u, h1 = 0u, h2 = 0u, h3 = 0u, h4 = 0u;
    float v1 = 0.0f, v2 = 0.0f, r = 0.0f;

    #pragma unroll 1
    for (int t0 = 0; t0 < T_STEPS; t0 += UF) {
        // front-batched streaming loads: 20 independent LDGs in flight
        float xv[UF];
        #pragma unroll
        for (int i = 0; i < UF; i++)
            xv[i] = __ldcs(xp + (size_t)(t0 + i) * TBN);

        #pragma unroll
        for (int i = 0; i < UF; i++) {
            unsigned nb = (xv[i] != 0.0f) ? 1u : 0u;
            h4 = ((h4 << 1) | (h3 >> 31)) & 0x001FFFFFu;
            h3 = (h3 << 1) | (h2 >> 31);
            h2 = (h2 << 1) | (h1 >> 31);
            h1 = (h1 << 1) | (h0 >> 31);
            h0 = (h0 << 1) | nb;

            // IIR approx of the conv (error ~1e-5 << MARGIN)
            float v = fmaf(c1, v1, fmaf(c2, v2, xv[i]));
            v -= (h1 & (1u << 18)) ? A : 0.0f;   // x[t-50]
            v -= (h3 & (1u << 4))  ? A : 0.0f;   // x[t-100]
            v2 = v1; v1 = v;

            float u = v + r;
            if (__builtin_expect(fabsf(u - 1.0f) < MARGIN, 0)) {
                // near threshold: recompute with the reference's exact f32
                // rounding — sum ks[j] over set bits, j descending 148..0.
                float acc = 0.0f;
                unsigned m;
                m = h4; while (m) { unsigned b = 31u - __clz(m); acc += ks[128 + b]; m &= ~(1u << b); }
                m = h3; while (m) { unsigned b = 31u - __clz(m); acc += ks[ 96 + b]; m &= ~(1u << b); }
                m = h2; while (m) { unsigned b = 31u - __clz(m); acc += ks[ 64 + b]; m &= ~(1u << b); }
                m = h1; while (m) { unsigned b = 31u - __clz(m); acc += ks[ 32 + b]; m &= ~(1u << b); }
                m = h0; while (m) { unsigned b = 31u - __clz(m); acc += ks[      b]; m &= ~(1u << b); }
                u = acc + r;
            }

            float s = (u >= 1.0f) ? 1.0f : 0.0f;
            r = (r - s) * alpha;
            __stcs(op + (size_t)(t0 + i) * TBN, s);
        }
    }
}

extern "C" void kernel_launch(void* const* d_in, const int* in_sizes, int n_in,
                              void* d_out, int out_size) {
    const float* x   = (const float*)d_in[0];  // binary_input (500,16,1,4096) f32
    const float* ker = (const float*)d_in[1];  // epsp_kernel (1,149) f32
    float* out = (float*)d_out;                // spikes (500,16,4096) f32
    SpikingLayer_90202903151092_kernel<<<TBN / BLK, BLK>>>(x, ker, out);
}